// round 11
// baseline (speedup 1.0000x reference)
#include <cuda_runtime.h>
#include <cuda_fp16.h>
#include <cstdint>

#define FDIM 1024
#define BATCH 8
#define SEQ 2048
#define MTOT (BATCH * SEQ)   // 16384
#define NQKV 3072            // concatenated Q|K|V columns

// ---------------- scratch (__device__ globals) ----------------
__device__ __half g_xh[MTOT * FDIM];
__device__ __half g_Wh[3][FDIM * FDIM];          // stacked = Wcat [3072,1024]
__device__ float  g_bcat[NQKV];
__device__ __half g_QKV[(size_t)MTOT * NQKV];    // [16384, 3072] = Q|K|V
__device__ __half g_Vth[BATCH * FDIM * SEQ];
__device__ __half g_Ph[(size_t)BATCH * SEQ * SEQ];
__device__ float  g_rs[MTOT];

// ---------------- PTX helpers ----------------
__device__ __forceinline__ uint32_t smem_to_u32(const void* p) {
    uint32_t a;
    asm("{ .reg .u64 t; cvta.to.shared.u64 t, %1; cvt.u32.u64 %0, t; }" : "=r"(a) : "l"(p));
    return a;
}
__device__ __forceinline__ void cp_async16(uint32_t dst, const void* src) {
    asm volatile("cp.async.cg.shared.global [%0], [%1], 16;" :: "r"(dst), "l"(src));
}
#define CP_COMMIT() asm volatile("cp.async.commit_group;" ::: "memory")
#define CP_WAIT0()  asm volatile("cp.async.wait_group 0;" ::: "memory")
#define CP_WAIT1()  asm volatile("cp.async.wait_group 1;" ::: "memory")

__device__ __forceinline__ void ldm4(uint32_t (&r)[4], uint32_t addr) {
    asm volatile("ldmatrix.sync.aligned.m8n8.x4.shared.b16 {%0,%1,%2,%3}, [%4];"
                 : "=r"(r[0]), "=r"(r[1]), "=r"(r[2]), "=r"(r[3]) : "r"(addr));
}
__device__ __forceinline__ void mma_f32(float (&d)[4], const uint32_t (&a)[4],
                                        uint32_t b0, uint32_t b1) {
    asm volatile("mma.sync.aligned.m16n8k16.row.col.f32.f16.f16.f32 "
                 "{%0,%1,%2,%3}, {%4,%5,%6,%7}, {%8,%9}, {%0,%1,%2,%3};"
                 : "+f"(d[0]), "+f"(d[1]), "+f"(d[2]), "+f"(d[3])
                 : "r"(a[0]), "r"(a[1]), "r"(a[2]), "r"(a[3]), "r"(b0), "r"(b1));
}

// ---------------- GEMM config ----------------
#define ROWPAD   80
#define NSTAGE   3

// C(MxN) = A(BMxK, stride lda) @ B(128xK, stride ldb)^T, batched via blockIdx.z.
// BM = 128 or 64. Warp tile (BM/2) x 32; 8 warps as 2m x 4n.
// omode 0: half out = acc + bias[cc]         (proj)
// omode 1: half out = expf(alpha * acc)      (unnormalized attention weights)
// omode 2: fp32 out = acc / rowsum[z*M + r]  (normalized P@V)
template <int BM>
__global__ __launch_bounds__(256) void gemm_mma(
    const __half* __restrict__ Ag, const __half* __restrict__ Bg,
    const float* __restrict__ bias, const float* __restrict__ rowsum,
    __half* __restrict__ outH, float* __restrict__ outF,
    int N, int Kd, int lda, int ldb, int ldc,
    float alpha, int omode,
    long long sA, long long sB, long long sC)
{
    constexpr int A_T = BM * ROWPAD;
    constexpr int B_T = 128 * ROWPAD;
    constexpr int STG = A_T + B_T;
    constexpr int MFRAG = BM / 32;          // m16 fragments per warp

    extern __shared__ char smem[];
    const uint32_t smem0 = smem_to_u32(smem);
    const int tid = threadIdx.x;
    const int wid = tid >> 5;
    const int lane = tid & 31;
    const int z = blockIdx.z;
    const long long row0 = (long long)blockIdx.x * BM;
    const long long col0 = (long long)blockIdx.y * 128;

    const __half* A = Ag + (long long)z * sA + row0 * lda;
    const __half* B = Bg + (long long)z * sB + col0 * ldb;

    const int warp_m0 = (wid >> 2) * (BM / 2);
    const int warp_n0 = (wid & 3) * 32;

    const uint32_t lmofs = (uint32_t)(lane & 15) * ROWPAD + (uint32_t)(lane >> 4) * 16;

    float acc[MFRAG][4][4];
    #pragma unroll
    for (int a = 0; a < MFRAG; a++)
        #pragma unroll
        for (int b = 0; b < 4; b++)
            #pragma unroll
            for (int cI = 0; cI < 4; cI++) acc[a][b][cI] = 0.0f;

    const int NC = Kd >> 5;   // BK=32

    // ---- pipelined loads ----
    auto load_chunk = [&](uint32_t st, long long kofs) {
        #pragma unroll
        for (int i = 0; i < BM * 4 / 256; i++) {
            int u = tid + i * 256;
            int row = u >> 2, seg = u & 3;
            cp_async16(st + row * ROWPAD + seg * 16,
                       A + (long long)row * lda + kofs + seg * 8);
        }
        #pragma unroll
        for (int i = 0; i < 2; i++) {
            int u = tid + i * 256;
            int row = u >> 2, seg = u & 3;
            cp_async16(st + A_T + row * ROWPAD + seg * 16,
                       B + (long long)row * ldb + kofs + seg * 8);
        }
        CP_COMMIT();
    };

    load_chunk(smem0, 0);
    load_chunk(smem0 + STG, 32);

    int stage = 0;
    for (int c = 0; c < NC; c++) {
        if (c + 1 < NC) CP_WAIT1(); else CP_WAIT0();
        __syncthreads();

        const uint32_t st = smem0 + stage * STG;
        const uint32_t tA = st, tB = st + A_T;

        #pragma unroll
        for (int ks = 0; ks < 2; ks++) {
            uint32_t af[MFRAG][4], bf[2][4];
            #pragma unroll
            for (int g = 0; g < MFRAG; g++) {
                uint32_t oa = (uint32_t)(warp_m0 + g * 16) * ROWPAD + ks * 32 + lmofs;
                ldm4(af[g], tA + oa);
            }
            #pragma unroll
            for (int g = 0; g < 2; g++) {
                uint32_t ob = (uint32_t)(warp_n0 + g * 16) * ROWPAD + ks * 32 + lmofs;
                ldm4(bf[g], tB + ob);
            }
            #pragma unroll
            for (int mf = 0; mf < MFRAG; mf++)
                #pragma unroll
                for (int g = 0; g < 2; g++)
                    #pragma unroll
                    for (int p = 0; p < 2; p++)
                        mma_f32(acc[mf][g * 2 + p], af[mf], bf[g][p], bf[g][p + 2]);
        }

        if (c + 2 < NC) {
            int ns = stage + 2; if (ns >= NSTAGE) ns -= NSTAGE;
            load_chunk(smem0 + ns * STG, (long long)(c + 2) * 32);
        }
        if (++stage == NSTAGE) stage = 0;
    }

    // ---- epilogue ----
    const int rbase = warp_m0 + (lane >> 2);
    const int cbase = warp_n0 + 2 * (lane & 3);
    #pragma unroll
    for (int mf = 0; mf < MFRAG; mf++) {
        #pragma unroll
        for (int h = 0; h < 2; h++) {
            const long long r = row0 + rbase + mf * 16 + h * 8;
            float invr = 1.0f;
            if (omode == 2) invr = 1.0f / rowsum[(long long)z * SEQ + r];
            #pragma unroll
            for (int nf = 0; nf < 4; nf++) {
                long long cc = col0 + cbase + nf * 8;
                float f0 = acc[mf][nf][h * 2 + 0];
                float f1 = acc[mf][nf][h * 2 + 1];
                if (omode == 0) {
                    f0 += bias[cc];
                    f1 += bias[cc + 1];
                    __half2 ph; ph.x = __float2half(f0); ph.y = __float2half(f1);
                    *(__half2*)(outH + r * (long long)ldc + cc) = ph;
                } else if (omode == 1) {
                    __half2 ph;
                    ph.x = __float2half(__expf(alpha * f0));
                    ph.y = __float2half(__expf(alpha * f1));
                    *(__half2*)(outH + (long long)z * sC + r * (long long)ldc + cc) = ph;
                } else {
                    long long o = (long long)z * sC + r * (long long)ldc + cc;
                    *(float2*)(outF + o) = make_float2(f0 * invr, f1 * invr);
                }
            }
        }
    }
}

// fp32 -> fp16
__global__ __launch_bounds__(256) void to_half(
    const float* __restrict__ src, __half* __restrict__ dst, int n)
{
    int i = (blockIdx.x * 256 + threadIdx.x) * 4;
    if (i >= n) return;
    float4 v = *(const float4*)(src + i);
    __half2 h0; h0.x = __float2half(v.x); h0.y = __float2half(v.y);
    __half2 h1; h1.x = __float2half(v.z); h1.y = __float2half(v.w);
    *(__half2*)(dst + i) = h0; *(__half2*)(dst + i + 2) = h1;
}

// bias concat: [bq | bk | bv]
__global__ void concat_bias(const float* bq, const float* bk, const float* bv,
                            float* bcat)
{
    int i = blockIdx.x * 256 + threadIdx.x;
    if (i >= NQKV) return;
    float v = (i < FDIM) ? bq[i] : (i < 2 * FDIM) ? bk[i - FDIM] : bv[i - 2 * FDIM];
    bcat[i] = v;
}

// Vt[b][d][s] = QKV[b*SEQ+s][2048 + d]
__global__ __launch_bounds__(256) void transpose_v(
    const __half* __restrict__ QKV, __half* __restrict__ Vth)
{
    __shared__ __half th[32][33];
    const int b = blockIdx.z;
    const int s0 = blockIdx.x * 32, d0 = blockIdx.y * 32;
    const int tx = threadIdx.x, ty = threadIdx.y;
    #pragma unroll
    for (int j = 0; j < 4; j++) {
        int r = ty + j * 8;
        th[r][tx] = QKV[(long long)(b * SEQ + s0 + r) * NQKV + 2048 + d0 + tx];
    }
    __syncthreads();
    #pragma unroll
    for (int j = 0; j < 4; j++) {
        int r = ty + j * 8;
        Vth[(long long)(b * FDIM + d0 + r) * SEQ + s0 + tx] = th[tx][r];
    }
}

// rowsum[r] = sum of P[r][0..SEQ)  (one warp per row)
__global__ __launch_bounds__(256) void row_sums(
    const __half* __restrict__ P, float* __restrict__ rs)
{
    const int row = blockIdx.x * 8 + (threadIdx.x >> 5);
    const int lane = threadIdx.x & 31;
    const __half2* p = (const __half2*)(P + (long long)row * SEQ);
    float s = 0.0f;
    #pragma unroll 8
    for (int i = lane; i < SEQ / 2; i += 32) {
        float2 f = __half22float2(p[i]);
        s += f.x + f.y;
    }
    #pragma unroll
    for (int o = 16; o > 0; o >>= 1) s += __shfl_xor_sync(0xFFFFFFFFu, s, o);
    if (lane == 0) rs[row] = s;
}

extern "C" void kernel_launch(void* const* d_in, const int* in_sizes, int n_in,
                              void* d_out, int out_size)
{
    const float* x  = (const float*)d_in[0];
    const float* Wq = (const float*)d_in[1];
    const float* bq = (const float*)d_in[2];
    const float* Wk = (const float*)d_in[3];
    const float* bk = (const float*)d_in[4];
    const float* Wv = (const float*)d_in[5];
    const float* bv = (const float*)d_in[6];
    float* out = (float*)d_out;

    const int SM128 = NSTAGE * (128 + 128) * ROWPAD;   // 61440
    const int SM64  = NSTAGE * (64 + 128) * ROWPAD;    // 46080
    cudaFuncSetAttribute(gemm_mma<128>, cudaFuncAttributeMaxDynamicSharedMemorySize, SM128);
    cudaFuncSetAttribute(gemm_mma<64>,  cudaFuncAttributeMaxDynamicSharedMemorySize, SM64);

    __half *xh, *Wh, *QKV, *Vth, *Ph;
    float *rs, *bcat;
    cudaGetSymbolAddress((void**)&xh, g_xh);
    cudaGetSymbolAddress((void**)&Wh, g_Wh);
    cudaGetSymbolAddress((void**)&bcat, g_bcat);
    cudaGetSymbolAddress((void**)&QKV, g_QKV);
    cudaGetSymbolAddress((void**)&Vth, g_Vth);
    cudaGetSymbolAddress((void**)&Ph, g_Ph);
    cudaGetSymbolAddress((void**)&rs, g_rs);

    const int NX = MTOT * FDIM;
    const int NW = FDIM * FDIM;
    const long long WSZ = (long long)FDIM * FDIM;

    to_half<<<NX / 4 / 256, 256>>>(x, xh, NX);
    to_half<<<NW / 4 / 256, 256>>>(Wq, Wh + 0 * WSZ, NW);
    to_half<<<NW / 4 / 256, 256>>>(Wk, Wh + 1 * WSZ, NW);
    to_half<<<NW / 4 / 256, 256>>>(Wv, Wh + 2 * WSZ, NW);
    concat_bias<<<(NQKV + 255) / 256, 256>>>(bq, bk, bv, bcat);

    // Merged QKV projection: [16384, 3072] = x @ Wcat^T + bcat  (single launch)
    dim3 g1(MTOT / 128, NQKV / 128, 1);
    gemm_mma<128><<<g1, 256, SM128>>>(xh, Wh, bcat, nullptr, QKV, nullptr,
                                      NQKV, FDIM, FDIM, FDIM, NQKV,
                                      1.0f, 0, 0, 0, 0);

    // P = exp(Q @ K^T / 32)  (fp16, unnormalized)
    dim3 g2(SEQ / 128, SEQ / 128, BATCH);
    gemm_mma<128><<<g2, 256, SM128>>>(QKV, QKV + FDIM, nullptr, nullptr, Ph, nullptr,
                                      SEQ, FDIM, NQKV, NQKV, SEQ,
                                      0.03125f, 1,
                                      (long long)SEQ * NQKV, (long long)SEQ * NQKV,
                                      (long long)SEQ * SEQ);

    transpose_v<<<dim3(SEQ / 32, FDIM / 32, BATCH), dim3(32, 8)>>>(QKV, Vth);

    row_sums<<<MTOT / 8, 256>>>(Ph, rs);

    // out = (P @ Vt^T) / rowsum  (fp32; BM=64 tiles -> 2048 CTAs, small tail)
    dim3 g3(SEQ / 64, FDIM / 128, BATCH);
    gemm_mma<64><<<g3, 256, SM64>>>(Ph, Vth, nullptr, rs, nullptr, out,
                                    FDIM, SEQ, SEQ, SEQ, FDIM,
                                    1.0f, 2,
                                    (long long)SEQ * SEQ, (long long)FDIM * SEQ,
                                    (long long)SEQ * FDIM);
}

// round 12
// speedup vs baseline: 1.0253x; 1.0253x over previous
#include <cuda_runtime.h>
#include <cuda_fp16.h>
#include <cstdint>

#define FDIM 1024
#define BATCH 8
#define SEQ 2048
#define MTOT (BATCH * SEQ)   // 16384
#define NQKV 3072            // concatenated Q|K|V columns

// ---------------- scratch (__device__ globals) ----------------
__device__ __half g_xh[MTOT * FDIM];
__device__ __half g_Wh[3][FDIM * FDIM];          // stacked = Wcat [3072,1024]
__device__ float  g_bcat[NQKV];
__device__ __half g_QKV[(size_t)MTOT * NQKV];    // [16384, 3072] = Q|K|V
__device__ __half g_Vth[BATCH * FDIM * SEQ];
__device__ __half g_Ph[(size_t)BATCH * SEQ * SEQ];
__device__ float  g_rs[MTOT];

// ---------------- PTX helpers ----------------
__device__ __forceinline__ uint32_t smem_to_u32(const void* p) {
    uint32_t a;
    asm("{ .reg .u64 t; cvta.to.shared.u64 t, %1; cvt.u32.u64 %0, t; }" : "=r"(a) : "l"(p));
    return a;
}
__device__ __forceinline__ void cp_async16(uint32_t dst, const void* src) {
    asm volatile("cp.async.cg.shared.global [%0], [%1], 16;" :: "r"(dst), "l"(src));
}
#define CP_COMMIT() asm volatile("cp.async.commit_group;" ::: "memory")
#define CP_WAIT0()  asm volatile("cp.async.wait_group 0;" ::: "memory")
#define CP_WAIT1()  asm volatile("cp.async.wait_group 1;" ::: "memory")

__device__ __forceinline__ void ldm4(uint32_t (&r)[4], uint32_t addr) {
    asm volatile("ldmatrix.sync.aligned.m8n8.x4.shared.b16 {%0,%1,%2,%3}, [%4];"
                 : "=r"(r[0]), "=r"(r[1]), "=r"(r[2]), "=r"(r[3]) : "r"(addr));
}
__device__ __forceinline__ void mma_f32(float (&d)[4], const uint32_t (&a)[4],
                                        uint32_t b0, uint32_t b1) {
    asm volatile("mma.sync.aligned.m16n8k16.row.col.f32.f16.f16.f32 "
                 "{%0,%1,%2,%3}, {%4,%5,%6,%7}, {%8,%9}, {%0,%1,%2,%3};"
                 : "+f"(d[0]), "+f"(d[1]), "+f"(d[2]), "+f"(d[3])
                 : "r"(a[0]), "r"(a[1]), "r"(a[2]), "r"(a[3]), "r"(b0), "r"(b1));
}

// ---------------- GEMM config ----------------
#define ROWPAD   80
#define TILE_B   (128 * ROWPAD)            // 10240
#define STAGE_B  (2 * TILE_B)              // 20480
#define NSTAGE   3
#define SMEM_SZ  (NSTAGE * STAGE_B)        // 61440

// C(MxN) = A(128xK, stride lda) @ B(128xK, stride ldb)^T, batched via blockIdx.z.
// 8 warps as 2m x 4n, warp tile 64x32.
// omode 0: half out = acc + bias[cc]         (proj)
// omode 1: half out = expf(alpha * acc)      (unnormalized attention weights)
// omode 2: fp32 out = acc / rowsum[z*M + r]  (normalized P@V)
__global__ __launch_bounds__(256) void gemm_mma(
    const __half* __restrict__ Ag, const __half* __restrict__ Bg,
    const float* __restrict__ bias, const float* __restrict__ rowsum,
    __half* __restrict__ outH, float* __restrict__ outF,
    int N, int Kd, int lda, int ldb, int ldc,
    float alpha, int omode,
    long long sA, long long sB, long long sC)
{
    extern __shared__ char smem[];
    const uint32_t smem0 = smem_to_u32(smem);
    const int tid = threadIdx.x;
    const int wid = tid >> 5;
    const int lane = tid & 31;
    const int z = blockIdx.z;
    const long long row0 = (long long)blockIdx.x * 128;
    const long long col0 = (long long)blockIdx.y * 128;

    const __half* A = Ag + (long long)z * sA + row0 * lda;
    const __half* B = Bg + (long long)z * sB + col0 * ldb;

    const int warp_m0 = (wid >> 2) * 64;   // 0,64
    const int warp_n0 = (wid & 3) * 32;    // 0,32,64,96

    const uint32_t lmofs = (uint32_t)(lane & 15) * ROWPAD + (uint32_t)(lane >> 4) * 16;

    float acc[4][4][4];
    #pragma unroll
    for (int a = 0; a < 4; a++)
        #pragma unroll
        for (int b = 0; b < 4; b++)
            #pragma unroll
            for (int cI = 0; cI < 4; cI++) acc[a][b][cI] = 0.0f;

    const int NC = Kd >> 5;   // BK=32

    auto load_chunk = [&](uint32_t st, long long kofs) {
        #pragma unroll
        for (int i = 0; i < 2; i++) {
            int u = tid + i * 256;
            int row = u >> 2, seg = u & 3;
            cp_async16(st + row * ROWPAD + seg * 16,
                       A + (long long)row * lda + kofs + seg * 8);
            cp_async16(st + TILE_B + row * ROWPAD + seg * 16,
                       B + (long long)row * ldb + kofs + seg * 8);
        }
        CP_COMMIT();
    };

    load_chunk(smem0, 0);
    load_chunk(smem0 + STAGE_B, 32);

    int stage = 0;
    for (int c = 0; c < NC; c++) {
        if (c + 1 < NC) CP_WAIT1(); else CP_WAIT0();
        __syncthreads();

        const uint32_t st = smem0 + stage * STAGE_B;
        const uint32_t tA = st, tB = st + TILE_B;

        #pragma unroll
        for (int ks = 0; ks < 2; ks++) {
            uint32_t af[4][4], bf[2][4];
            #pragma unroll
            for (int g = 0; g < 4; g++) {
                uint32_t oa = (uint32_t)(warp_m0 + g * 16) * ROWPAD + ks * 32 + lmofs;
                ldm4(af[g], tA + oa);
            }
            #pragma unroll
            for (int g = 0; g < 2; g++) {
                uint32_t ob = (uint32_t)(warp_n0 + g * 16) * ROWPAD + ks * 32 + lmofs;
                ldm4(bf[g], tB + ob);
            }
            #pragma unroll
            for (int mf = 0; mf < 4; mf++)
                #pragma unroll
                for (int g = 0; g < 2; g++)
                    #pragma unroll
                    for (int p = 0; p < 2; p++)
                        mma_f32(acc[mf][g * 2 + p], af[mf], bf[g][p], bf[g][p + 2]);
        }

        if (c + 2 < NC) {
            int ns = stage + 2; if (ns >= NSTAGE) ns -= NSTAGE;
            load_chunk(smem0 + ns * STAGE_B, (long long)(c + 2) * 32);
        }
        if (++stage == NSTAGE) stage = 0;
    }

    // ---- epilogue ----
    const int rbase = warp_m0 + (lane >> 2);
    const int cbase = warp_n0 + 2 * (lane & 3);
    #pragma unroll
    for (int mf = 0; mf < 4; mf++) {
        #pragma unroll
        for (int h = 0; h < 2; h++) {
            const long long r = row0 + rbase + mf * 16 + h * 8;
            float invr = 1.0f;
            if (omode == 2) invr = 1.0f / rowsum[(long long)z * SEQ + r];
            #pragma unroll
            for (int nf = 0; nf < 4; nf++) {
                long long cc = col0 + cbase + nf * 8;
                float f0 = acc[mf][nf][h * 2 + 0];
                float f1 = acc[mf][nf][h * 2 + 1];
                if (omode == 0) {
                    f0 += bias[cc];
                    f1 += bias[cc + 1];
                    __half2 ph; ph.x = __float2half(f0); ph.y = __float2half(f1);
                    *(__half2*)(outH + r * (long long)ldc + cc) = ph;
                } else if (omode == 1) {
                    __half2 ph;
                    ph.x = __float2half(__expf(alpha * f0));
                    ph.y = __float2half(__expf(alpha * f1));
                    *(__half2*)(outH + (long long)z * sC + r * (long long)ldc + cc) = ph;
                } else {
                    long long o = (long long)z * sC + r * (long long)ldc + cc;
                    *(float2*)(outF + o) = make_float2(f0 * invr, f1 * invr);
                }
            }
        }
    }
}

// fp32 -> fp16
__global__ __launch_bounds__(256) void to_half(
    const float* __restrict__ src, __half* __restrict__ dst, int n)
{
    int i = (blockIdx.x * 256 + threadIdx.x) * 4;
    if (i >= n) return;
    float4 v = *(const float4*)(src + i);
    __half2 h0; h0.x = __float2half(v.x); h0.y = __float2half(v.y);
    __half2 h1; h1.x = __float2half(v.z); h1.y = __float2half(v.w);
    *(__half2*)(dst + i) = h0; *(__half2*)(dst + i + 2) = h1;
}

// bias concat: [bq | bk | bv]
__global__ void concat_bias(const float* bq, const float* bk, const float* bv,
                            float* bcat)
{
    int i = blockIdx.x * 256 + threadIdx.x;
    if (i >= NQKV) return;
    float v = (i < FDIM) ? bq[i] : (i < 2 * FDIM) ? bk[i - FDIM] : bv[i - 2 * FDIM];
    bcat[i] = v;
}

// Vt[b][d][s] = QKV[b*SEQ+s][2048 + d]
__global__ __launch_bounds__(256) void transpose_v(
    const __half* __restrict__ QKV, __half* __restrict__ Vth)
{
    __shared__ __half th[32][33];
    const int b = blockIdx.z;
    const int s0 = blockIdx.x * 32, d0 = blockIdx.y * 32;
    const int tx = threadIdx.x, ty = threadIdx.y;
    #pragma unroll
    for (int j = 0; j < 4; j++) {
        int r = ty + j * 8;
        th[r][tx] = QKV[(long long)(b * SEQ + s0 + r) * NQKV + 2048 + d0 + tx];
    }
    __syncthreads();
    #pragma unroll
    for (int j = 0; j < 4; j++) {
        int r = ty + j * 8;
        Vth[(long long)(b * FDIM + d0 + r) * SEQ + s0 + tx] = th[tx][r];
    }
}

// rowsum[r] = sum of P[r][0..SEQ)  (one warp per row)
__global__ __launch_bounds__(256) void row_sums(
    const __half* __restrict__ P, float* __restrict__ rs)
{
    const int row = blockIdx.x * 8 + (threadIdx.x >> 5);
    const int lane = threadIdx.x & 31;
    const __half2* p = (const __half2*)(P + (long long)row * SEQ);
    float s = 0.0f;
    #pragma unroll 8
    for (int i = lane; i < SEQ / 2; i += 32) {
        float2 f = __half22float2(p[i]);
        s += f.x + f.y;
    }
    #pragma unroll
    for (int o = 16; o > 0; o >>= 1) s += __shfl_xor_sync(0xFFFFFFFFu, s, o);
    if (lane == 0) rs[row] = s;
}

extern "C" void kernel_launch(void* const* d_in, const int* in_sizes, int n_in,
                              void* d_out, int out_size)
{
    const float* x  = (const float*)d_in[0];
    const float* Wq = (const float*)d_in[1];
    const float* bq = (const float*)d_in[2];
    const float* Wk = (const float*)d_in[3];
    const float* bk = (const float*)d_in[4];
    const float* Wv = (const float*)d_in[5];
    const float* bv = (const float*)d_in[6];
    float* out = (float*)d_out;

    cudaFuncSetAttribute(gemm_mma, cudaFuncAttributeMaxDynamicSharedMemorySize, SMEM_SZ);

    __half *xh, *Wh, *QKV, *Vth, *Ph;
    float *rs, *bcat;
    cudaGetSymbolAddress((void**)&xh, g_xh);
    cudaGetSymbolAddress((void**)&Wh, g_Wh);
    cudaGetSymbolAddress((void**)&bcat, g_bcat);
    cudaGetSymbolAddress((void**)&QKV, g_QKV);
    cudaGetSymbolAddress((void**)&Vth, g_Vth);
    cudaGetSymbolAddress((void**)&Ph, g_Ph);
    cudaGetSymbolAddress((void**)&rs, g_rs);

    const int NX = MTOT * FDIM;
    const int NW = FDIM * FDIM;
    const long long WSZ = (long long)FDIM * FDIM;

    to_half<<<NX / 4 / 256, 256>>>(x, xh, NX);
    to_half<<<NW / 4 / 256, 256>>>(Wq, Wh + 0 * WSZ, NW);
    to_half<<<NW / 4 / 256, 256>>>(Wk, Wh + 1 * WSZ, NW);
    to_half<<<NW / 4 / 256, 256>>>(Wv, Wh + 2 * WSZ, NW);
    concat_bias<<<(NQKV + 255) / 256, 256>>>(bq, bk, bv, bcat);

    // Merged QKV projection: [16384, 3072] = x @ Wcat^T + bcat  (single launch)
    dim3 g1(MTOT / 128, NQKV / 128, 1);
    gemm_mma<<<g1, 256, SMEM_SZ>>>(xh, Wh, bcat, nullptr, QKV, nullptr,
                                   NQKV, FDIM, FDIM, FDIM, NQKV,
                                   1.0f, 0, 0, 0, 0);

    // P = exp(Q @ K^T / 32)  (fp16, unnormalized)
    dim3 g2(SEQ / 128, SEQ / 128, BATCH);
    gemm_mma<<<g2, 256, SMEM_SZ>>>(QKV, QKV + FDIM, nullptr, nullptr, Ph, nullptr,
                                   SEQ, FDIM, NQKV, NQKV, SEQ,
                                   0.03125f, 1,
                                   (long long)SEQ * NQKV, (long long)SEQ * NQKV,
                                   (long long)SEQ * SEQ);

    transpose_v<<<dim3(SEQ / 32, FDIM / 32, BATCH), dim3(32, 8)>>>(QKV, Vth);

    row_sums<<<MTOT / 8, 256>>>(Ph, rs);

    // out = (P @ Vt^T) / rowsum  (fp32 out; BM=128 tiles as in R10)
    dim3 g3(SEQ / 128, FDIM / 128, BATCH);
    gemm_mma<<<g3, 256, SMEM_SZ>>>(Ph, Vth, nullptr, rs, nullptr, out,
                                   FDIM, SEQ, SEQ, SEQ, FDIM,
                                   1.0f, 2,
                                   (long long)SEQ * SEQ, (long long)FDIM * SEQ,
                                   (long long)SEQ * FDIM);
}

// round 13
// speedup vs baseline: 1.0530x; 1.0270x over previous
#include <cuda_runtime.h>
#include <cuda_fp16.h>
#include <cstdint>

#define FDIM 1024
#define BATCH 8
#define SEQ 2048
#define MTOT (BATCH * SEQ)   // 16384
#define NQKV 3072            // concatenated Q|K|V columns

// Q pre-scale so scores epilogue is a bare ex2: p = 2^(Q'.K) = exp(Q.K/32)
#define QSCALE 0.04508422002778633f   // log2(e) / 32

// ---------------- scratch (__device__ globals) ----------------
__device__ __half g_xh[MTOT * FDIM];
__device__ __half g_Wh[3][FDIM * FDIM];          // stacked = Wcat [3072,1024]
__device__ float  g_bcat[NQKV];                  // pre-scaled bias
__device__ __half g_QKV[(size_t)MTOT * NQKV];    // [16384, 3072] = Q'|K|V
__device__ __half g_Vth[BATCH * FDIM * SEQ];
__device__ __half g_Ph[(size_t)BATCH * SEQ * SEQ];
__device__ float  g_rs[MTOT];

// ---------------- PTX helpers ----------------
__device__ __forceinline__ uint32_t smem_to_u32(const void* p) {
    uint32_t a;
    asm("{ .reg .u64 t; cvta.to.shared.u64 t, %1; cvt.u32.u64 %0, t; }" : "=r"(a) : "l"(p));
    return a;
}
__device__ __forceinline__ void cp_async16(uint32_t dst, const void* src) {
    asm volatile("cp.async.cg.shared.global [%0], [%1], 16;" :: "r"(dst), "l"(src));
}
#define CP_COMMIT() asm volatile("cp.async.commit_group;" ::: "memory")
#define CP_WAIT0()  asm volatile("cp.async.wait_group 0;" ::: "memory")
#define CP_WAIT1()  asm volatile("cp.async.wait_group 1;" ::: "memory")

__device__ __forceinline__ void ldm4(uint32_t (&r)[4], uint32_t addr) {
    asm volatile("ldmatrix.sync.aligned.m8n8.x4.shared.b16 {%0,%1,%2,%3}, [%4];"
                 : "=r"(r[0]), "=r"(r[1]), "=r"(r[2]), "=r"(r[3]) : "r"(addr));
}
__device__ __forceinline__ void mma_f32(float (&d)[4], const uint32_t (&a)[4],
                                        uint32_t b0, uint32_t b1) {
    asm volatile("mma.sync.aligned.m16n8k16.row.col.f32.f16.f16.f32 "
                 "{%0,%1,%2,%3}, {%4,%5,%6,%7}, {%8,%9}, {%0,%1,%2,%3};"
                 : "+f"(d[0]), "+f"(d[1]), "+f"(d[2]), "+f"(d[3])
                 : "r"(a[0]), "r"(a[1]), "r"(a[2]), "r"(a[3]), "r"(b0), "r"(b1));
}
__device__ __forceinline__ float ex2f(float x) {
    float y;
    asm("ex2.approx.ftz.f32 %0, %1;" : "=f"(y) : "f"(x));
    return y;
}

// ---------------- GEMM config ----------------
#define ROWPAD   80
#define TILE_B   (128 * ROWPAD)            // 10240
#define STAGE_B  (2 * TILE_B)              // 20480
#define NSTAGE   3
#define SMEM_SZ  (NSTAGE * STAGE_B)        // 61440

// C(MxN) = A(128xK, stride lda) @ B(128xK, stride ldb)^T, batched via blockIdx.z.
// 8 warps as 2m x 4n, warp tile 64x32.
// omode 0: half out = fma(acc, colScale, bias'[cc])   (proj; Q cols scaled by QSCALE)
// omode 1: half out = ex2(acc)                        (unnormalized attention weights)
// omode 2: fp32 out = acc / rowsum[z*M + r]           (normalized P@V)
__global__ __launch_bounds__(256) void gemm_mma(
    const __half* __restrict__ Ag, const __half* __restrict__ Bg,
    const float* __restrict__ bias, const float* __restrict__ rowsum,
    __half* __restrict__ outH, float* __restrict__ outF,
    int N, int Kd, int lda, int ldb, int ldc,
    int omode,
    long long sA, long long sB, long long sC)
{
    extern __shared__ char smem[];
    const uint32_t smem0 = smem_to_u32(smem);
    const int tid = threadIdx.x;
    const int wid = tid >> 5;
    const int lane = tid & 31;
    const int z = blockIdx.z;
    const long long row0 = (long long)blockIdx.x * 128;
    const long long col0 = (long long)blockIdx.y * 128;

    const __half* A = Ag + (long long)z * sA + row0 * lda;
    const __half* B = Bg + (long long)z * sB + col0 * ldb;

    const int warp_m0 = (wid >> 2) * 64;   // 0,64
    const int warp_n0 = (wid & 3) * 32;    // 0,32,64,96

    const uint32_t lmofs = (uint32_t)(lane & 15) * ROWPAD + (uint32_t)(lane >> 4) * 16;

    float acc[4][4][4];
    #pragma unroll
    for (int a = 0; a < 4; a++)
        #pragma unroll
        for (int b = 0; b < 4; b++)
            #pragma unroll
            for (int cI = 0; cI < 4; cI++) acc[a][b][cI] = 0.0f;

    const int NC = Kd >> 5;   // BK=32

    auto load_chunk = [&](uint32_t st, long long kofs) {
        #pragma unroll
        for (int i = 0; i < 2; i++) {
            int u = tid + i * 256;
            int row = u >> 2, seg = u & 3;
            cp_async16(st + row * ROWPAD + seg * 16,
                       A + (long long)row * lda + kofs + seg * 8);
            cp_async16(st + TILE_B + row * ROWPAD + seg * 16,
                       B + (long long)row * ldb + kofs + seg * 8);
        }
        CP_COMMIT();
    };

    load_chunk(smem0, 0);
    load_chunk(smem0 + STAGE_B, 32);

    int stage = 0;
    for (int c = 0; c < NC; c++) {
        if (c + 1 < NC) CP_WAIT1(); else CP_WAIT0();
        __syncthreads();

        const uint32_t st = smem0 + stage * STAGE_B;
        const uint32_t tA = st, tB = st + TILE_B;

        #pragma unroll
        for (int ks = 0; ks < 2; ks++) {
            uint32_t af[4][4], bf[2][4];
            #pragma unroll
            for (int g = 0; g < 4; g++) {
                uint32_t oa = (uint32_t)(warp_m0 + g * 16) * ROWPAD + ks * 32 + lmofs;
                ldm4(af[g], tA + oa);
            }
            #pragma unroll
            for (int g = 0; g < 2; g++) {
                uint32_t ob = (uint32_t)(warp_n0 + g * 16) * ROWPAD + ks * 32 + lmofs;
                ldm4(bf[g], tB + ob);
            }
            #pragma unroll
            for (int mf = 0; mf < 4; mf++)
                #pragma unroll
                for (int g = 0; g < 2; g++)
                    #pragma unroll
                    for (int p = 0; p < 2; p++)
                        mma_f32(acc[mf][g * 2 + p], af[mf], bf[g][p], bf[g][p + 2]);
        }

        if (c + 2 < NC) {
            int ns = stage + 2; if (ns >= NSTAGE) ns -= NSTAGE;
            load_chunk(smem0 + ns * STAGE_B, (long long)(c + 2) * 32);
        }
        if (++stage == NSTAGE) stage = 0;
    }

    // ---- epilogue ----
    const int rbase = warp_m0 + (lane >> 2);
    const int cbase = warp_n0 + 2 * (lane & 3);
    #pragma unroll
    for (int mf = 0; mf < 4; mf++) {
        #pragma unroll
        for (int h = 0; h < 2; h++) {
            const long long r = row0 + rbase + mf * 16 + h * 8;
            float invr = 1.0f;
            if (omode == 2) invr = 1.0f / rowsum[(long long)z * SEQ + r];
            #pragma unroll
            for (int nf = 0; nf < 4; nf++) {
                long long cc = col0 + cbase + nf * 8;
                float f0 = acc[mf][nf][h * 2 + 0];
                float f1 = acc[mf][nf][h * 2 + 1];
                if (omode == 0) {
                    // per-column scale: Q columns folded with QSCALE, bias pre-scaled
                    float sc = (cc < FDIM) ? QSCALE : 1.0f;
                    f0 = fmaf(f0, sc, bias[cc]);
                    f1 = fmaf(f1, sc, bias[cc + 1]);
                    *(__half2*)(outH + r * (long long)ldc + cc) =
                        __floats2half2_rn(f0, f1);
                } else if (omode == 1) {
                    *(__half2*)(outH + (long long)z * sC + r * (long long)ldc + cc) =
                        __floats2half2_rn(ex2f(f0), ex2f(f1));
                } else {
                    long long o = (long long)z * sC + r * (long long)ldc + cc;
                    *(float2*)(outF + o) = make_float2(f0 * invr, f1 * invr);
                }
            }
        }
    }
}

// fp32 -> fp16
__global__ __launch_bounds__(256) void to_half(
    const float* __restrict__ src, __half* __restrict__ dst, int n)
{
    int i = (blockIdx.x * 256 + threadIdx.x) * 4;
    if (i >= n) return;
    float4 v = *(const float4*)(src + i);
    *(__half2*)(dst + i)     = __floats2half2_rn(v.x, v.y);
    *(__half2*)(dst + i + 2) = __floats2half2_rn(v.z, v.w);
}

// bias concat with Q pre-scale: [bq*QSCALE | bk | bv]
__global__ void concat_bias(const float* bq, const float* bk, const float* bv,
                            float* bcat)
{
    int i = blockIdx.x * 256 + threadIdx.x;
    if (i >= NQKV) return;
    float v = (i < FDIM) ? bq[i] * QSCALE
            : (i < 2 * FDIM) ? bk[i - FDIM] : bv[i - 2 * FDIM];
    bcat[i] = v;
}

// Vt[b][d][s] = QKV[b*SEQ+s][2048 + d]
__global__ __launch_bounds__(256) void transpose_v(
    const __half* __restrict__ QKV, __half* __restrict__ Vth)
{
    __shared__ __half th[32][33];
    const int b = blockIdx.z;
    const int s0 = blockIdx.x * 32, d0 = blockIdx.y * 32;
    const int tx = threadIdx.x, ty = threadIdx.y;
    #pragma unroll
    for (int j = 0; j < 4; j++) {
        int r = ty + j * 8;
        th[r][tx] = QKV[(long long)(b * SEQ + s0 + r) * NQKV + 2048 + d0 + tx];
    }
    __syncthreads();
    #pragma unroll
    for (int j = 0; j < 4; j++) {
        int r = ty + j * 8;
        Vth[(long long)(b * FDIM + d0 + r) * SEQ + s0 + tx] = th[tx][r];
    }
}

// rowsum[r] = sum of P[r][0..SEQ)  (one warp per row)
__global__ __launch_bounds__(256) void row_sums(
    const __half* __restrict__ P, float* __restrict__ rs)
{
    const int row = blockIdx.x * 8 + (threadIdx.x >> 5);
    const int lane = threadIdx.x & 31;
    const __half2* p = (const __half2*)(P + (long long)row * SEQ);
    float s = 0.0f;
    #pragma unroll 8
    for (int i = lane; i < SEQ / 2; i += 32) {
        float2 f = __half22float2(p[i]);
        s += f.x + f.y;
    }
    #pragma unroll
    for (int o = 16; o > 0; o >>= 1) s += __shfl_xor_sync(0xFFFFFFFFu, s, o);
    if (lane == 0) rs[row] = s;
}

extern "C" void kernel_launch(void* const* d_in, const int* in_sizes, int n_in,
                              void* d_out, int out_size)
{
    const float* x  = (const float*)d_in[0];
    const float* Wq = (const float*)d_in[1];
    const float* bq = (const float*)d_in[2];
    const float* Wk = (const float*)d_in[3];
    const float* bk = (const float*)d_in[4];
    const float* Wv = (const float*)d_in[5];
    const float* bv = (const float*)d_in[6];
    float* out = (float*)d_out;

    cudaFuncSetAttribute(gemm_mma, cudaFuncAttributeMaxDynamicSharedMemorySize, SMEM_SZ);

    __half *xh, *Wh, *QKV, *Vth, *Ph;
    float *rs, *bcat;
    cudaGetSymbolAddress((void**)&xh, g_xh);
    cudaGetSymbolAddress((void**)&Wh, g_Wh);
    cudaGetSymbolAddress((void**)&bcat, g_bcat);
    cudaGetSymbolAddress((void**)&QKV, g_QKV);
    cudaGetSymbolAddress((void**)&Vth, g_Vth);
    cudaGetSymbolAddress((void**)&Ph, g_Ph);
    cudaGetSymbolAddress((void**)&rs, g_rs);

    const int NX = MTOT * FDIM;
    const int NW = FDIM * FDIM;
    const long long WSZ = (long long)FDIM * FDIM;

    to_half<<<NX / 4 / 256, 256>>>(x, xh, NX);
    to_half<<<NW / 4 / 256, 256>>>(Wq, Wh + 0 * WSZ, NW);
    to_half<<<NW / 4 / 256, 256>>>(Wk, Wh + 1 * WSZ, NW);
    to_half<<<NW / 4 / 256, 256>>>(Wv, Wh + 2 * WSZ, NW);
    concat_bias<<<(NQKV + 255) / 256, 256>>>(bq, bk, bv, bcat);

    // Merged QKV projection; Q columns scaled by QSCALE = log2(e)/32
    dim3 g1(MTOT / 128, NQKV / 128, 1);
    gemm_mma<<<g1, 256, SMEM_SZ>>>(xh, Wh, bcat, nullptr, QKV, nullptr,
                                   NQKV, FDIM, FDIM, FDIM, NQKV,
                                   0, 0, 0, 0);

    // P = 2^(Q' @ K^T) = exp(Q @ K^T / 32)  (fp16, unnormalized)
    dim3 g2(SEQ / 128, SEQ / 128, BATCH);
    gemm_mma<<<g2, 256, SMEM_SZ>>>(QKV, QKV + FDIM, nullptr, nullptr, Ph, nullptr,
                                   SEQ, FDIM, NQKV, NQKV, SEQ,
                                   1,
                                   (long long)SEQ * NQKV, (long long)SEQ * NQKV,
                                   (long long)SEQ * SEQ);

    transpose_v<<<dim3(SEQ / 32, FDIM / 32, BATCH), dim3(32, 8)>>>(QKV, Vth);

    row_sums<<<MTOT / 8, 256>>>(Ph, rs);

    // out = (P @ Vt^T) / rowsum  (fp32 out)
    dim3 g3(SEQ / 128, FDIM / 128, BATCH);
    gemm_mma<<<g3, 256, SMEM_SZ>>>(Ph, Vth, nullptr, rs, nullptr, out,
                                   FDIM, SEQ, SEQ, SEQ, FDIM,
                                   2,
                                   (long long)SEQ * SEQ, (long long)FDIM * SEQ,
                                   (long long)SEQ * FDIM);
}

// round 14
// speedup vs baseline: 1.0580x; 1.0048x over previous
#include <cuda_runtime.h>
#include <cuda_fp16.h>
#include <cstdint>

#define FDIM 1024
#define BATCH 8
#define SEQ 2048
#define MTOT (BATCH * SEQ)   // 16384
#define NQKV 3072            // concatenated Q|K|V columns

// Q pre-scale so scores epilogue is a bare ex2: p = 2^(Q'.K) = exp(Q.K/32)
#define QSCALE 0.04508422002778633f   // log2(e) / 32

// ---------------- scratch (__device__ globals) ----------------
__device__ __half g_xh[MTOT * FDIM];
__device__ __half g_Wh[3][FDIM * FDIM];          // stacked = Wcat [3072,1024]
__device__ float  g_bcat[NQKV];                  // pre-scaled bias
__device__ __half g_QKV[(size_t)MTOT * NQKV];    // [16384, 3072] = Q'|K|V
__device__ __half g_Vth[BATCH * FDIM * SEQ];
__device__ __half g_Ph[(size_t)BATCH * SEQ * SEQ];
__device__ float  g_rsp[(size_t)MTOT * 64];      // per-(row, n-warp-tile) partial sums
__device__ float  g_rs[MTOT];                    // reciprocal row sums

// ---------------- PTX helpers ----------------
__device__ __forceinline__ uint32_t smem_to_u32(const void* p) {
    uint32_t a;
    asm("{ .reg .u64 t; cvta.to.shared.u64 t, %1; cvt.u32.u64 %0, t; }" : "=r"(a) : "l"(p));
    return a;
}
__device__ __forceinline__ void cp_async16(uint32_t dst, const void* src) {
    asm volatile("cp.async.cg.shared.global [%0], [%1], 16;" :: "r"(dst), "l"(src));
}
#define CP_COMMIT() asm volatile("cp.async.commit_group;" ::: "memory")
#define CP_WAIT0()  asm volatile("cp.async.wait_group 0;" ::: "memory")
#define CP_WAIT1()  asm volatile("cp.async.wait_group 1;" ::: "memory")

__device__ __forceinline__ void ldm4(uint32_t (&r)[4], uint32_t addr) {
    asm volatile("ldmatrix.sync.aligned.m8n8.x4.shared.b16 {%0,%1,%2,%3}, [%4];"
                 : "=r"(r[0]), "=r"(r[1]), "=r"(r[2]), "=r"(r[3]) : "r"(addr));
}
__device__ __forceinline__ void mma_f32(float (&d)[4], const uint32_t (&a)[4],
                                        uint32_t b0, uint32_t b1) {
    asm volatile("mma.sync.aligned.m16n8k16.row.col.f32.f16.f16.f32 "
                 "{%0,%1,%2,%3}, {%4,%5,%6,%7}, {%8,%9}, {%0,%1,%2,%3};"
                 : "+f"(d[0]), "+f"(d[1]), "+f"(d[2]), "+f"(d[3])
                 : "r"(a[0]), "r"(a[1]), "r"(a[2]), "r"(a[3]), "r"(b0), "r"(b1));
}
__device__ __forceinline__ float ex2f(float x) {
    float y;
    asm("ex2.approx.ftz.f32 %0, %1;" : "=f"(y) : "f"(x));
    return y;
}

// ---------------- GEMM config ----------------
#define ROWPAD   80
#define TILE_B   (128 * ROWPAD)            // 10240
#define STAGE_B  (2 * TILE_B)              // 20480
#define NSTAGE   3
#define SMEM_SZ  (NSTAGE * STAGE_B)        // 61440

// C(MxN) = A(128xK, stride lda) @ B(128xK, stride ldb)^T, batched via blockIdx.z.
// 8 warps as 2m x 4n, warp tile 64x32.
// omode 0: half out = fma(acc, colScale, bias'[cc])   (proj; Q cols scaled by QSCALE)
// omode 1: half out = ex2(acc); also writes per-(row,tile) partial sums
// omode 2: fp32 out = acc * rinv[z*M + r]             (normalized P@V)
__global__ __launch_bounds__(256) void gemm_mma(
    const __half* __restrict__ Ag, const __half* __restrict__ Bg,
    const float* __restrict__ bias, const float* __restrict__ rinv,
    float* __restrict__ partials,
    __half* __restrict__ outH, float* __restrict__ outF,
    int N, int Kd, int lda, int ldb, int ldc,
    int omode,
    long long sA, long long sB, long long sC)
{
    extern __shared__ char smem[];
    const uint32_t smem0 = smem_to_u32(smem);
    const int tid = threadIdx.x;
    const int wid = tid >> 5;
    const int lane = tid & 31;
    const int z = blockIdx.z;
    const long long row0 = (long long)blockIdx.x * 128;
    const long long col0 = (long long)blockIdx.y * 128;

    const __half* A = Ag + (long long)z * sA + row0 * lda;
    const __half* B = Bg + (long long)z * sB + col0 * ldb;

    const int warp_m0 = (wid >> 2) * 64;   // 0,64
    const int warp_n0 = (wid & 3) * 32;    // 0,32,64,96

    const uint32_t lmofs = (uint32_t)(lane & 15) * ROWPAD + (uint32_t)(lane >> 4) * 16;

    float acc[4][4][4];
    #pragma unroll
    for (int a = 0; a < 4; a++)
        #pragma unroll
        for (int b = 0; b < 4; b++)
            #pragma unroll
            for (int cI = 0; cI < 4; cI++) acc[a][b][cI] = 0.0f;

    const int NC = Kd >> 5;   // BK=32

    auto load_chunk = [&](uint32_t st, long long kofs) {
        #pragma unroll
        for (int i = 0; i < 2; i++) {
            int u = tid + i * 256;
            int row = u >> 2, seg = u & 3;
            cp_async16(st + row * ROWPAD + seg * 16,
                       A + (long long)row * lda + kofs + seg * 8);
            cp_async16(st + TILE_B + row * ROWPAD + seg * 16,
                       B + (long long)row * ldb + kofs + seg * 8);
        }
        CP_COMMIT();
    };

    load_chunk(smem0, 0);
    load_chunk(smem0 + STAGE_B, 32);

    int stage = 0;
    for (int c = 0; c < NC; c++) {
        if (c + 1 < NC) CP_WAIT1(); else CP_WAIT0();
        __syncthreads();

        const uint32_t st = smem0 + stage * STAGE_B;
        const uint32_t tA = st, tB = st + TILE_B;

        #pragma unroll
        for (int ks = 0; ks < 2; ks++) {
            uint32_t af[4][4], bf[2][4];
            #pragma unroll
            for (int g = 0; g < 4; g++) {
                uint32_t oa = (uint32_t)(warp_m0 + g * 16) * ROWPAD + ks * 32 + lmofs;
                ldm4(af[g], tA + oa);
            }
            #pragma unroll
            for (int g = 0; g < 2; g++) {
                uint32_t ob = (uint32_t)(warp_n0 + g * 16) * ROWPAD + ks * 32 + lmofs;
                ldm4(bf[g], tB + ob);
            }
            #pragma unroll
            for (int mf = 0; mf < 4; mf++)
                #pragma unroll
                for (int g = 0; g < 2; g++)
                    #pragma unroll
                    for (int p = 0; p < 2; p++)
                        mma_f32(acc[mf][g * 2 + p], af[mf], bf[g][p], bf[g][p + 2]);
        }

        if (c + 2 < NC) {
            int ns = stage + 2; if (ns >= NSTAGE) ns -= NSTAGE;
            load_chunk(smem0 + ns * STAGE_B, (long long)(c + 2) * 32);
        }
        if (++stage == NSTAGE) stage = 0;
    }

    // ---- epilogue ----
    const int rbase = warp_m0 + (lane >> 2);
    const int cbase = warp_n0 + 2 * (lane & 3);
    float rsum[4][2];
    #pragma unroll
    for (int mf = 0; mf < 4; mf++) { rsum[mf][0] = 0.0f; rsum[mf][1] = 0.0f; }

    #pragma unroll
    for (int mf = 0; mf < 4; mf++) {
        #pragma unroll
        for (int h = 0; h < 2; h++) {
            const long long r = row0 + rbase + mf * 16 + h * 8;
            float invr = 1.0f;
            if (omode == 2) invr = rinv[(long long)z * SEQ + r];
            #pragma unroll
            for (int nf = 0; nf < 4; nf++) {
                long long cc = col0 + cbase + nf * 8;
                float f0 = acc[mf][nf][h * 2 + 0];
                float f1 = acc[mf][nf][h * 2 + 1];
                if (omode == 0) {
                    float sc = (cc < FDIM) ? QSCALE : 1.0f;
                    f0 = fmaf(f0, sc, bias[cc]);
                    f1 = fmaf(f1, sc, bias[cc + 1]);
                    *(__half2*)(outH + r * (long long)ldc + cc) =
                        __floats2half2_rn(f0, f1);
                } else if (omode == 1) {
                    float e0 = ex2f(f0), e1 = ex2f(f1);
                    rsum[mf][h] += e0 + e1;
                    *(__half2*)(outH + (long long)z * sC + r * (long long)ldc + cc) =
                        __floats2half2_rn(e0, e1);
                } else {
                    long long o = (long long)z * sC + r * (long long)ldc + cc;
                    *(float2*)(outF + o) = make_float2(f0 * invr, f1 * invr);
                }
            }
        }
    }

    if (omode == 1) {
        // reduce across the 4 same-row lanes (bits 0-1 of lane), write partial
        #pragma unroll
        for (int mf = 0; mf < 4; mf++) {
            #pragma unroll
            for (int h = 0; h < 2; h++) {
                float s = rsum[mf][h];
                s += __shfl_xor_sync(0xFFFFFFFFu, s, 1);
                s += __shfl_xor_sync(0xFFFFFFFFu, s, 2);
                if ((lane & 3) == 0) {
                    long long r = (long long)z * SEQ + row0 + rbase + mf * 16 + h * 8;
                    partials[r * 64 + blockIdx.y * 4 + (wid & 3)] = s;
                }
            }
        }
    }
}

// fp32 -> fp16
__global__ __launch_bounds__(256) void to_half(
    const float* __restrict__ src, __half* __restrict__ dst, int n)
{
    int i = (blockIdx.x * 256 + threadIdx.x) * 4;
    if (i >= n) return;
    float4 v = *(const float4*)(src + i);
    *(__half2*)(dst + i)     = __floats2half2_rn(v.x, v.y);
    *(__half2*)(dst + i + 2) = __floats2half2_rn(v.z, v.w);
}

// bias concat with Q pre-scale: [bq*QSCALE | bk | bv]
__global__ void concat_bias(const float* bq, const float* bk, const float* bv,
                            float* bcat)
{
    int i = blockIdx.x * 256 + threadIdx.x;
    if (i >= NQKV) return;
    float v = (i < FDIM) ? bq[i] * QSCALE
            : (i < 2 * FDIM) ? bk[i - FDIM] : bv[i - 2 * FDIM];
    bcat[i] = v;
}

// Vt[b][d][s] = QKV[b*SEQ+s][2048 + d]
__global__ __launch_bounds__(256) void transpose_v(
    const __half* __restrict__ QKV, __half* __restrict__ Vth)
{
    __shared__ __half th[32][33];
    const int b = blockIdx.z;
    const int s0 = blockIdx.x * 32, d0 = blockIdx.y * 32;
    const int tx = threadIdx.x, ty = threadIdx.y;
    #pragma unroll
    for (int j = 0; j < 4; j++) {
        int r = ty + j * 8;
        th[r][tx] = QKV[(long long)(b * SEQ + s0 + r) * NQKV + 2048 + d0 + tx];
    }
    __syncthreads();
    #pragma unroll
    for (int j = 0; j < 4; j++) {
        int r = ty + j * 8;
        Vth[(long long)(b * FDIM + d0 + r) * SEQ + s0 + tx] = th[tx][r];
    }
}

// rs[row] = 1 / sum(partials[row][0..64))   (one warp per row)
__global__ __launch_bounds__(256) void rs_reduce(
    const float* __restrict__ partials, float* __restrict__ rs)
{
    const int row = blockIdx.x * 8 + (threadIdx.x >> 5);
    const int lane = threadIdx.x & 31;
    const float* p = partials + (long long)row * 64;
    float s = p[lane] + p[lane + 32];
    #pragma unroll
    for (int o = 16; o > 0; o >>= 1) s += __shfl_xor_sync(0xFFFFFFFFu, s, o);
    if (lane == 0) rs[row] = 1.0f / s;
}

extern "C" void kernel_launch(void* const* d_in, const int* in_sizes, int n_in,
                              void* d_out, int out_size)
{
    const float* x  = (const float*)d_in[0];
    const float* Wq = (const float*)d_in[1];
    const float* bq = (const float*)d_in[2];
    const float* Wk = (const float*)d_in[3];
    const float* bk = (const float*)d_in[4];
    const float* Wv = (const float*)d_in[5];
    const float* bv = (const float*)d_in[6];
    float* out = (float*)d_out;

    cudaFuncSetAttribute(gemm_mma, cudaFuncAttributeMaxDynamicSharedMemorySize, SMEM_SZ);

    __half *xh, *Wh, *QKV, *Vth, *Ph;
    float *rs, *rsp, *bcat;
    cudaGetSymbolAddress((void**)&xh, g_xh);
    cudaGetSymbolAddress((void**)&Wh, g_Wh);
    cudaGetSymbolAddress((void**)&bcat, g_bcat);
    cudaGetSymbolAddress((void**)&QKV, g_QKV);
    cudaGetSymbolAddress((void**)&Vth, g_Vth);
    cudaGetSymbolAddress((void**)&Ph, g_Ph);
    cudaGetSymbolAddress((void**)&rsp, g_rsp);
    cudaGetSymbolAddress((void**)&rs, g_rs);

    const int NX = MTOT * FDIM;
    const int NW = FDIM * FDIM;
    const long long WSZ = (long long)FDIM * FDIM;

    // fork resources (host-side creation is capture-legal)
    cudaStream_t sB;
    cudaStreamCreateWithFlags(&sB, cudaStreamNonBlocking);
    cudaEvent_t evP, evT;
    cudaEventCreateWithFlags(&evP, cudaEventDisableTiming);
    cudaEventCreateWithFlags(&evT, cudaEventDisableTiming);

    to_half<<<NX / 4 / 256, 256>>>(x, xh, NX);
    to_half<<<NW / 4 / 256, 256>>>(Wq, Wh + 0 * WSZ, NW);
    to_half<<<NW / 4 / 256, 256>>>(Wk, Wh + 1 * WSZ, NW);
    to_half<<<NW / 4 / 256, 256>>>(Wv, Wh + 2 * WSZ, NW);
    concat_bias<<<(NQKV + 255) / 256, 256>>>(bq, bk, bv, bcat);

    // Merged QKV projection; Q columns scaled by QSCALE = log2(e)/32
    dim3 g1(MTOT / 128, NQKV / 128, 1);
    gemm_mma<<<g1, 256, SMEM_SZ>>>(xh, Wh, bcat, nullptr, nullptr, QKV, nullptr,
                                   NQKV, FDIM, FDIM, FDIM, NQKV,
                                   0, 0, 0, 0);
    cudaEventRecord(evP, 0);

    // stream B: V transpose, concurrent with scores GEMM
    cudaStreamWaitEvent(sB, evP, 0);
    transpose_v<<<dim3(SEQ / 32, FDIM / 32, BATCH), dim3(32, 8), 0, sB>>>(QKV, Vth);
    cudaEventRecord(evT, sB);

    // P = 2^(Q' @ K^T) (fp16, unnormalized) + fused per-tile row sums
    dim3 g2(SEQ / 128, SEQ / 128, BATCH);
    gemm_mma<<<g2, 256, SMEM_SZ>>>(QKV, QKV + FDIM, nullptr, nullptr, rsp, Ph, nullptr,
                                   SEQ, FDIM, NQKV, NQKV, SEQ,
                                   1,
                                   (long long)SEQ * NQKV, (long long)SEQ * NQKV,
                                   (long long)SEQ * SEQ);

    rs_reduce<<<MTOT / 8, 256>>>(rsp, rs);

    cudaStreamWaitEvent(0, evT, 0);   // PV needs Vth

    // out = (P @ Vt^T) * rinv  (fp32 out)
    dim3 g3(SEQ / 128, FDIM / 128, BATCH);
    gemm_mma<<<g3, 256, SMEM_SZ>>>(Ph, Vth, nullptr, rs, nullptr, nullptr, out,
                                   FDIM, SEQ, SEQ, SEQ, FDIM,
                                   2,
                                   (long long)SEQ * SEQ, (long long)FDIM * SEQ,
                                   (long long)SEQ * FDIM);
}

// round 16
// speedup vs baseline: 1.0782x; 1.0190x over previous
#include <cuda_runtime.h>
#include <cuda_fp16.h>
#include <cstdint>

#define FDIM 1024
#define BATCH 8
#define SEQ 2048
#define MTOT (BATCH * SEQ)   // 16384
#define NQKV 3072            // concatenated Q|K|V columns

// Q pre-scale so scores epilogue is a bare ex2: p = 2^(Q'.K) = exp(Q.K/32)
#define QSCALE 0.04508422002778633f   // log2(e) / 32

// ---------------- scratch (__device__ globals) ----------------
__device__ __half g_xh[MTOT * FDIM];
__device__ __half g_Wh[3][FDIM * FDIM];          // stacked = Wcat [3072,1024]
__device__ float  g_bcat[NQKV];                  // pre-scaled bias
__device__ __half g_QKV[(size_t)MTOT * NQKV];    // [16384, 3072] = Q'|K|V
__device__ __half g_Vth[BATCH * FDIM * SEQ];
__device__ __half g_Ph[(size_t)BATCH * SEQ * SEQ];
__device__ float  g_rsp[(size_t)MTOT * 64];      // per-(row, n-warp-tile) partial sums
__device__ float  g_rs[MTOT];                    // reciprocal row sums

// ---------------- PTX helpers ----------------
__device__ __forceinline__ uint32_t smem_to_u32(const void* p) {
    uint32_t a;
    asm("{ .reg .u64 t; cvta.to.shared.u64 t, %1; cvt.u32.u64 %0, t; }" : "=r"(a) : "l"(p));
    return a;
}
__device__ __forceinline__ void cp_async16(uint32_t dst, const void* src) {
    asm volatile("cp.async.cg.shared.global [%0], [%1], 16;" :: "r"(dst), "l"(src));
}
#define CP_COMMIT() asm volatile("cp.async.commit_group;" ::: "memory")
#define CP_WAIT0()  asm volatile("cp.async.wait_group 0;" ::: "memory")
#define CP_WAIT1()  asm volatile("cp.async.wait_group 1;" ::: "memory")
#define CP_WAIT2()  asm volatile("cp.async.wait_group 2;" ::: "memory")

__device__ __forceinline__ void ldm4(uint32_t (&r)[4], uint32_t addr) {
    asm volatile("ldmatrix.sync.aligned.m8n8.x4.shared.b16 {%0,%1,%2,%3}, [%4];"
                 : "=r"(r[0]), "=r"(r[1]), "=r"(r[2]), "=r"(r[3]) : "r"(addr));
}
__device__ __forceinline__ void mma_f32(float (&d)[4], const uint32_t (&a)[4],
                                        uint32_t b0, uint32_t b1) {
    asm volatile("mma.sync.aligned.m16n8k16.row.col.f32.f16.f16.f32 "
                 "{%0,%1,%2,%3}, {%4,%5,%6,%7}, {%8,%9}, {%0,%1,%2,%3};"
                 : "+f"(d[0]), "+f"(d[1]), "+f"(d[2]), "+f"(d[3])
                 : "r"(a[0]), "r"(a[1]), "r"(a[2]), "r"(a[3]), "r"(b0), "r"(b1));
}
__device__ __forceinline__ float ex2f(float x) {
    float y;
    asm("ex2.approx.ftz.f32 %0, %1;" : "=f"(y) : "f"(x));
    return y;
}

// ---------------- GEMM config ----------------
#define ROWPAD   80
#define TILE_B   (128 * ROWPAD)            // 10240
#define STAGE_B  (2 * TILE_B)              // 20480
#define NSTAGE   4
#define SMEM_SZ  (NSTAGE * STAGE_B)        // 81920

// C(MxN) = A(128xK, stride lda) @ B(128xK, stride ldb)^T, batched via blockIdx.z.
// 8 warps as 2m x 4n, warp tile 64x32.
// omode 0: half out = fma(acc, colScale, bias'[cc])   (proj; Q cols scaled by QSCALE)
// omode 1: half out = ex2(acc); also writes per-(row,tile) partial sums
// omode 2: fp32 out = acc * rinv[z*M + r]             (normalized P@V)
__global__ __launch_bounds__(256) void gemm_mma(
    const __half* __restrict__ Ag, const __half* __restrict__ Bg,
    const float* __restrict__ bias, const float* __restrict__ rinv,
    float* __restrict__ partials,
    __half* __restrict__ outH, float* __restrict__ outF,
    int N, int Kd, int lda, int ldb, int ldc,
    int omode,
    long long sA, long long sB, long long sC)
{
    extern __shared__ char smem[];
    const uint32_t smem0 = smem_to_u32(smem);
    const int tid = threadIdx.x;
    const int wid = tid >> 5;
    const int lane = tid & 31;
    const int z = blockIdx.z;
    const long long row0 = (long long)blockIdx.x * 128;
    const long long col0 = (long long)blockIdx.y * 128;

    const __half* A = Ag + (long long)z * sA + row0 * lda;
    const __half* B = Bg + (long long)z * sB + col0 * ldb;

    const int warp_m0 = (wid >> 2) * 64;   // 0,64
    const int warp_n0 = (wid & 3) * 32;    // 0,32,64,96

    const uint32_t lmofs = (uint32_t)(lane & 15) * ROWPAD + (uint32_t)(lane >> 4) * 16;

    float acc[4][4][4];
    #pragma unroll
    for (int a = 0; a < 4; a++)
        #pragma unroll
        for (int b = 0; b < 4; b++)
            #pragma unroll
            for (int cI = 0; cI < 4; cI++) acc[a][b][cI] = 0.0f;

    const int NC = Kd >> 5;   // BK=32

    auto load_chunk = [&](uint32_t st, long long kofs) {
        #pragma unroll
        for (int i = 0; i < 2; i++) {
            int u = tid + i * 256;
            int row = u >> 2, seg = u & 3;
            cp_async16(st + row * ROWPAD + seg * 16,
                       A + (long long)row * lda + kofs + seg * 8);
            cp_async16(st + TILE_B + row * ROWPAD + seg * 16,
                       B + (long long)row * ldb + kofs + seg * 8);
        }
        CP_COMMIT();
    };

    // prologue: 3 chunks in flight
    load_chunk(smem0, 0);
    if (NC > 1) load_chunk(smem0 + STAGE_B, 32);
    if (NC > 2) load_chunk(smem0 + 2 * STAGE_B, 64);

    int stage = 0;
    for (int c = 0; c < NC; c++) {
        const int pend = NC - 1 - c;          // outstanding newer loads
        if (pend >= 2) CP_WAIT2();
        else if (pend == 1) CP_WAIT1();
        else CP_WAIT0();
        __syncthreads();

        const uint32_t st = smem0 + stage * STAGE_B;
        const uint32_t tA = st, tB = st + TILE_B;

        #pragma unroll
        for (int ks = 0; ks < 2; ks++) {
            uint32_t af[4][4], bf[2][4];
            #pragma unroll
            for (int g = 0; g < 4; g++) {
                uint32_t oa = (uint32_t)(warp_m0 + g * 16) * ROWPAD + ks * 32 + lmofs;
                ldm4(af[g], tA + oa);
            }
            #pragma unroll
            for (int g = 0; g < 2; g++) {
                uint32_t ob = (uint32_t)(warp_n0 + g * 16) * ROWPAD + ks * 32 + lmofs;
                ldm4(bf[g], tB + ob);
            }
            #pragma unroll
            for (int mf = 0; mf < 4; mf++)
                #pragma unroll
                for (int g = 0; g < 2; g++)
                    #pragma unroll
                    for (int p = 0; p < 2; p++)
                        mma_f32(acc[mf][g * 2 + p], af[mf], bf[g][p], bf[g][p + 2]);
        }

        if (c + 3 < NC) {
            int ns = stage + 3; if (ns >= NSTAGE) ns -= NSTAGE;
            load_chunk(smem0 + ns * STAGE_B, (long long)(c + 3) * 32);
        }
        if (++stage == NSTAGE) stage = 0;
    }

    // ---- epilogue ----
    const int rbase = warp_m0 + (lane >> 2);
    const int cbase = warp_n0 + 2 * (lane & 3);
    float rsum[4][2];
    #pragma unroll
    for (int mf = 0; mf < 4; mf++) { rsum[mf][0] = 0.0f; rsum[mf][1] = 0.0f; }

    #pragma unroll
    for (int mf = 0; mf < 4; mf++) {
        #pragma unroll
        for (int h = 0; h < 2; h++) {
            const long long r = row0 + rbase + mf * 16 + h * 8;
            float invr = 1.0f;
            if (omode == 2) invr = rinv[(long long)z * SEQ + r];
            #pragma unroll
            for (int nf = 0; nf < 4; nf++) {
                long long cc = col0 + cbase + nf * 8;
                float f0 = acc[mf][nf][h * 2 + 0];
                float f1 = acc[mf][nf][h * 2 + 1];
                if (omode == 0) {
                    float sc = (cc < FDIM) ? QSCALE : 1.0f;
                    f0 = fmaf(f0, sc, bias[cc]);
                    f1 = fmaf(f1, sc, bias[cc + 1]);
                    *(__half2*)(outH + r * (long long)ldc + cc) =
                        __floats2half2_rn(f0, f1);
                } else if (omode == 1) {
                    float e0 = ex2f(f0), e1 = ex2f(f1);
                    rsum[mf][h] += e0 + e1;
                    *(__half2*)(outH + (long long)z * sC + r * (long long)ldc + cc) =
                        __floats2half2_rn(e0, e1);
                } else {
                    long long o = (long long)z * sC + r * (long long)ldc + cc;
                    *(float2*)(outF + o) = make_float2(f0 * invr, f1 * invr);
                }
            }
        }
    }

    if (omode == 1) {
        // reduce across the 4 same-row lanes (bits 0-1 of lane), write partial
        #pragma unroll
        for (int mf = 0; mf < 4; mf++) {
            #pragma unroll
            for (int h = 0; h < 2; h++) {
                float s = rsum[mf][h];
                s += __shfl_xor_sync(0xFFFFFFFFu, s, 1);
                s += __shfl_xor_sync(0xFFFFFFFFu, s, 2);
                if ((lane & 3) == 0) {
                    long long r = (long long)z * SEQ + row0 + rbase + mf * 16 + h * 8;
                    partials[r * 64 + blockIdx.y * 4 + (wid & 3)] = s;
                }
            }
        }
    }
}

// fp32 -> fp16
__global__ __launch_bounds__(256) void to_half(
    const float* __restrict__ src, __half* __restrict__ dst, int n)
{
    int i = (blockIdx.x * 256 + threadIdx.x) * 4;
    if (i >= n) return;
    float4 v = *(const float4*)(src + i);
    *(__half2*)(dst + i)     = __floats2half2_rn(v.x, v.y);
    *(__half2*)(dst + i + 2) = __floats2half2_rn(v.z, v.w);
}

// convert all three W matrices (each NW = 2^20 elems) in one launch
__global__ __launch_bounds__(256) void w_convert(
    const float* __restrict__ Wq, const float* __restrict__ Wk,
    const float* __restrict__ Wv, __half* __restrict__ dst)
{
    int i = (blockIdx.x * 256 + threadIdx.x) * 4;
    int w = i >> 20;                        // NW = 1<<20
    int off = i & ((1 << 20) - 1);
    const float* src = (w == 0) ? Wq : (w == 1) ? Wk : Wv;
    float4 v = *(const float4*)(src + off);
    *(__half2*)(dst + i)     = __floats2half2_rn(v.x, v.y);
    *(__half2*)(dst + i + 2) = __floats2half2_rn(v.z, v.w);
}

// bias concat with Q pre-scale: [bq*QSCALE | bk | bv]
__global__ void concat_bias(const float* bq, const float* bk, const float* bv,
                            float* bcat)
{
    int i = blockIdx.x * 256 + threadIdx.x;
    if (i >= NQKV) return;
    float v = (i < FDIM) ? bq[i] * QSCALE
            : (i < 2 * FDIM) ? bk[i - FDIM] : bv[i - 2 * FDIM];
    bcat[i] = v;
}

// Vt[b][d][s] = QKV[b*SEQ+s][2048 + d]
__global__ __launch_bounds__(256) void transpose_v(
    const __half* __restrict__ QKV, __half* __restrict__ Vth)
{
    __shared__ __half th[32][33];
    const int b = blockIdx.z;
    const int s0 = blockIdx.x * 32, d0 = blockIdx.y * 32;
    const int tx = threadIdx.x, ty = threadIdx.y;
    #pragma unroll
    for (int j = 0; j < 4; j++) {
        int r = ty + j * 8;
        th[r][tx] = QKV[(long long)(b * SEQ + s0 + r) * NQKV + 2048 + d0 + tx];
    }
    __syncthreads();
    #pragma unroll
    for (int j = 0; j < 4; j++) {
        int r = ty + j * 8;
        Vth[(long long)(b * FDIM + d0 + r) * SEQ + s0 + tx] = th[tx][r];
    }
}

// rs[row] = 1 / sum(partials[row][0..64))   (one warp per row)
__global__ __launch_bounds__(256) void rs_reduce(
    const float* __restrict__ partials, float* __restrict__ rs)
{
    const int row = blockIdx.x * 8 + (threadIdx.x >> 5);
    const int lane = threadIdx.x & 31;
    const float* p = partials + (long long)row * 64;
    float s = p[lane] + p[lane + 32];
    #pragma unroll
    for (int o = 16; o > 0; o >>= 1) s += __shfl_xor_sync(0xFFFFFFFFu, s, o);
    if (lane == 0) rs[row] = 1.0f / s;
}

extern "C" void kernel_launch(void* const* d_in, const int* in_sizes, int n_in,
                              void* d_out, int out_size)
{
    const float* x  = (const float*)d_in[0];
    const float* Wq = (const float*)d_in[1];
    const float* bq = (const float*)d_in[2];
    const float* Wk = (const float*)d_in[3];
    const float* bk = (const float*)d_in[4];
    const float* Wv = (const float*)d_in[5];
    const float* bv = (const float*)d_in[6];
    float* out = (float*)d_out;

    cudaFuncSetAttribute(gemm_mma, cudaFuncAttributeMaxDynamicSharedMemorySize, SMEM_SZ);

    __half *xh, *Wh, *QKV, *Vth, *Ph;
    float *rs, *rsp, *bcat;
    cudaGetSymbolAddress((void**)&xh, g_xh);
    cudaGetSymbolAddress((void**)&Wh, g_Wh);
    cudaGetSymbolAddress((void**)&bcat, g_bcat);
    cudaGetSymbolAddress((void**)&QKV, g_QKV);
    cudaGetSymbolAddress((void**)&Vth, g_Vth);
    cudaGetSymbolAddress((void**)&Ph, g_Ph);
    cudaGetSymbolAddress((void**)&rsp, g_rsp);
    cudaGetSymbolAddress((void**)&rs, g_rs);

    const int NX = MTOT * FDIM;
    const int NW = FDIM * FDIM;

    // fork resources (host-side creation is capture-legal)
    cudaStream_t sB;
    cudaStreamCreateWithFlags(&sB, cudaStreamNonBlocking);
    cudaEvent_t evF, evX, evP, evT;
    cudaEventCreateWithFlags(&evF, cudaEventDisableTiming);
    cudaEventCreateWithFlags(&evX, cudaEventDisableTiming);
    cudaEventCreateWithFlags(&evP, cudaEventDisableTiming);
    cudaEventCreateWithFlags(&evT, cudaEventDisableTiming);

    // PROPER capture fork: sB must first wait on an event recorded in the
    // origin stream before any work is launched on it.
    cudaEventRecord(evF, 0);
    cudaStreamWaitEvent(sB, evF, 0);

    // x-convert on side stream, W-convert + bias on main, concurrent
    to_half<<<NX / 4 / 256, 256, 0, sB>>>(x, xh, NX);
    cudaEventRecord(evX, sB);
    w_convert<<<3 * NW / 4 / 256, 256>>>(Wq, Wk, Wv, Wh);
    concat_bias<<<(NQKV + 255) / 256, 256>>>(bq, bk, bv, bcat);
    cudaStreamWaitEvent(0, evX, 0);

    // Merged QKV projection; Q columns scaled by QSCALE = log2(e)/32
    dim3 g1(MTOT / 128, NQKV / 128, 1);
    gemm_mma<<<g1, 256, SMEM_SZ>>>(xh, Wh, bcat, nullptr, nullptr, QKV, nullptr,
                                   NQKV, FDIM, FDIM, FDIM, NQKV,
                                   0, 0, 0, 0);
    cudaEventRecord(evP, 0);

    // stream B: V transpose, concurrent with scores GEMM
    cudaStreamWaitEvent(sB, evP, 0);
    transpose_v<<<dim3(SEQ / 32, FDIM / 32, BATCH), dim3(32, 8), 0, sB>>>(QKV, Vth);
    cudaEventRecord(evT, sB);

    // P = 2^(Q' @ K^T) (fp16, unnormalized) + fused per-tile row sums
    dim3 g2(SEQ / 128, SEQ / 128, BATCH);
    gemm_mma<<<g2, 256, SMEM_SZ>>>(QKV, QKV + FDIM, nullptr, nullptr, rsp, Ph, nullptr,
                                   SEQ, FDIM, NQKV, NQKV, SEQ,
                                   1,
                                   (long long)SEQ * NQKV, (long long)SEQ * NQKV,
                                   (long long)SEQ * SEQ);

    rs_reduce<<<MTOT / 8, 256>>>(rsp, rs);

    cudaStreamWaitEvent(0, evT, 0);   // PV needs Vth

    // out = (P @ Vt^T) * rinv  (fp32 out)
    dim3 g3(SEQ / 128, FDIM / 128, BATCH);
    gemm_mma<<<g3, 256, SMEM_SZ>>>(Ph, Vth, nullptr, rs, nullptr, nullptr, out,
                                   FDIM, SEQ, SEQ, SEQ, FDIM,
                                   2,
                                   (long long)SEQ * SEQ, (long long)FDIM * SEQ,
                                   (long long)SEQ * FDIM);
}